// round 7
// baseline (speedup 1.0000x reference)
#include <cuda_runtime.h>
#include <cstdint>

// Conv2d N=32, CIN=3, H=W=224, COUT=64, 3x3, s1, p1, fp32.
// Implicit GEMM via mma.sync.m16n8k16 bf16->f32, 3-pass hi/lo fp32 emulation.
// R6: fix R5 off-by-one — staged window per channel must cover index
// SOFF+225+rel_max+8 = 964, so SIN=968 (was 964, causing cross-channel /
// OOB reads for the last pixel of each block).

#define NN 32
#define HWDIM 224
#define IMG (HWDIM*HWDIM)        // 50176
#define COUT 64
#define CIN 3
#define NTHREADS 128
#define PX_PER_BLOCK 512
#define ITERS 8
#define BLKS_PER_IMG (IMG/PX_PER_BLOCK)   // 98
#define SIN 968                  // staged floats per channel (242 float4)
#define SOFF 228                 // s_in[ch][o] <-> global px = P - SOFF + o
#define TPAD 20                  // transpose buffer px-stride (16 px + 4 pad)

__device__ __forceinline__ uint32_t cvt_bf16x2(float hi, float lo) {
    uint32_t d;
    asm("cvt.rn.bf16x2.f32 %0, %1, %2;" : "=r"(d) : "f"(hi), "f"(lo));
    return d;
}
__device__ __forceinline__ void mma_bf16(float* d, const uint32_t* a, const uint32_t* b) {
    asm volatile(
        "mma.sync.aligned.m16n8k16.row.col.f32.bf16.bf16.f32 "
        "{%0,%1,%2,%3}, {%4,%5,%6,%7}, {%8,%9}, {%0,%1,%2,%3};"
        : "+f"(d[0]), "+f"(d[1]), "+f"(d[2]), "+f"(d[3])
        : "r"(a[0]), "r"(a[1]), "r"(a[2]), "r"(a[3]), "r"(b[0]), "r"(b[1]));
}

__global__ __launch_bounds__(NTHREADS, 3)
void conv_mma(const float* __restrict__ xin, const float* __restrict__ wgt,
              const float* __restrict__ bias, float* __restrict__ out)
{
    __shared__ __align__(16) float s_in[CIN * SIN];        // 11616 B
    __shared__ __align__(16) float s_tr[4 * COUT * TPAD];  // 20480 B

    const int tid  = threadIdx.x;
    const int warp = tid >> 5;
    const int lane = tid & 31;
    const int lg   = lane >> 2;     // 0..7
    const int c    = (lane & 3) * 2;

    const int n   = blockIdx.x / BLKS_PER_IMG;
    const int blk = blockIdx.x % BLKS_PER_IMG;
    const int P   = blk * PX_PER_BLOCK;
    const float* in_n  = xin + (size_t)n * (CIN * IMG);
    float*       out_n = out + (size_t)n * (COUT * IMG);

    // ---- stage input range [P-228, P+740) per channel, zero-filled OOB ----
    for (int i = tid; i < CIN * (SIN / 4); i += NTHREADS) {
        const int ch = i / (SIN / 4);
        const int o  = (i % (SIN / 4)) * 4;
        const int g  = P - SOFF + o;
        const float* src = in_n + ch * IMG;
        float4 v;
        if (g >= 0 && g + 4 <= IMG) {
            v = *reinterpret_cast<const float4*>(src + g);
        } else {
            v.x = ((unsigned)(g    ) < (unsigned)IMG) ? src[g]     : 0.f;
            v.y = ((unsigned)(g + 1) < (unsigned)IMG) ? src[g + 1] : 0.f;
            v.z = ((unsigned)(g + 2) < (unsigned)IMG) ? src[g + 2] : 0.f;
            v.w = ((unsigned)(g + 3) < (unsigned)IMG) ? src[g + 3] : 0.f;
        }
        *reinterpret_cast<float4*>(&s_in[ch * SIN + o]) = v;
    }

    // ---- B (weight+bias) fragments, hi/lo, once per thread ----
    uint32_t BH[8][2][2], BL[8][2][2];
#pragma unroll
    for (int nt = 0; nt < 8; ++nt) {
        const int co = nt * 8 + lg;
#pragma unroll
        for (int s = 0; s < 2; ++s)
#pragma unroll
        for (int r = 0; r < 2; ++r) {
            const int k0 = 16 * s + c + 8 * r;
            const int k1 = k0 + 1;
            const float f0 = (k0 < 27) ? wgt[co * 27 + k0] : (k0 == 27 ? bias[co] : 0.f);
            const float f1 = (k1 < 27) ? wgt[co * 27 + k1] : (k1 == 27 ? bias[co] : 0.f);
            const uint32_t h = cvt_bf16x2(f1, f0);
            const float l0 = f0 - __uint_as_float(h << 16);
            const float l1 = f1 - __uint_as_float(h & 0xffff0000u);
            BH[nt][s][r] = h;
            BL[nt][s][r] = cvt_bf16x2(l1, l0);
        }
    }

    // ---- tap setup: k = c + offs[t] ----
    const int offs[8] = {0, 1, 8, 9, 16, 17, 24, 25};
    int   tapoff[8], dxi[8];
    bool  valid[8];
    float fdef[8];                 // select value when tap unusable
#pragma unroll
    for (int t = 0; t < 8; ++t) {
        const int k = c + offs[t];
        valid[t] = (k < 27);
        const int kk = valid[t] ? k : 0;
        const int ci = kk / 9, r = kk % 9;
        const int dy = r / 3 - 1, dx = r % 3 - 1;
        tapoff[t] = ci * SIN + SOFF + dy * HWDIM + dx;
        dxi[t]    = dx + 1;
        fdef[t]   = (k == 27) ? 1.f : 0.f;   // used only when !valid
    }

    float* tb = &s_tr[warp * COUT * TPAD];
    __syncthreads();

    for (int it = 0; it < ITERS; ++it) {
        const int rel = it * 64 + warp * 16 + lg;   // p0 - P
        const int x0  = (P + rel) % HWDIM;

        // x-edge predicates per dx (y-edges are zero-filled in s_in)
        bool e0[3], e1[3];
        e0[0] = (x0 >= 1);   e0[1] = true;        e0[2] = (x0 <= 222);
        e1[0] = (x0 <= 216); e1[1] = (x0 <= 215); e1[2] = (x0 <= 214);

        // ---- gather 8 taps x 2 pixels from smem ----
        float v0[8], v1[8];
#pragma unroll
        for (int t = 0; t < 8; ++t) {
            const int a = tapoff[t] + rel;
            const float la = s_in[a];
            const float lb = s_in[a + 8];
            const float d  = valid[t] ? 0.f : fdef[t];
            v0[t] = (valid[t] && e0[dxi[t]]) ? la : d;
            v1[t] = (valid[t] && e1[dxi[t]]) ? lb : d;
        }

        // ---- split hi/lo, pack A fragments ----
        uint32_t AH[2][4], AL[2][4];
#pragma unroll
        for (int s = 0; s < 2; ++s)
#pragma unroll
        for (int r = 0; r < 2; ++r) {
            const int t0 = 4 * s + 2 * r;
            const float f00 = v0[t0], f01 = v0[t0 + 1];
            const float f10 = v1[t0], f11 = v1[t0 + 1];
            const uint32_t h0 = cvt_bf16x2(f01, f00);
            const uint32_t h1 = cvt_bf16x2(f11, f10);
            AH[s][2 * r]     = h0;
            AH[s][2 * r + 1] = h1;
            const float l00 = f00 - __uint_as_float(h0 << 16);
            const float l01 = f01 - __uint_as_float(h0 & 0xffff0000u);
            const float l10 = f10 - __uint_as_float(h1 << 16);
            const float l11 = f11 - __uint_as_float(h1 & 0xffff0000u);
            AL[s][2 * r]     = cvt_bf16x2(l01, l00);
            AL[s][2 * r + 1] = cvt_bf16x2(l11, l10);
        }

        // ---- 48 MMAs ----
        float acc[8][4];
#pragma unroll
        for (int nt = 0; nt < 8; ++nt) {
            acc[nt][0] = 0.f; acc[nt][1] = 0.f; acc[nt][2] = 0.f; acc[nt][3] = 0.f;
        }
#pragma unroll
        for (int nt = 0; nt < 8; ++nt) {
#pragma unroll
            for (int s = 0; s < 2; ++s) {
                mma_bf16(acc[nt], AH[s], BH[nt][s]);
                mma_bf16(acc[nt], AH[s], BL[nt][s]);
                mma_bf16(acc[nt], AL[s], BH[nt][s]);
            }
        }

        // ---- transpose epilogue: acc -> [co][px] smem -> STG.128 ----
        __syncwarp();
#pragma unroll
        for (int nt = 0; nt < 8; ++nt) {
            const int co = nt * 8 + c;
            tb[(co    ) * TPAD + lg    ] = acc[nt][0];
            tb[(co + 1) * TPAD + lg    ] = acc[nt][1];
            tb[(co    ) * TPAD + lg + 8] = acc[nt][2];
            tb[(co + 1) * TPAD + lg + 8] = acc[nt][3];
        }
        __syncwarp();

        const int tilebase = P + it * 64 + warp * 16;
#pragma unroll
        for (int i = 0; i < 8; ++i) {
            const int co = i * 8 + (lane >> 2);
            const int px = (lane & 3) * 4;
            const float4 v = *reinterpret_cast<const float4*>(&tb[co * TPAD + px]);
            *reinterpret_cast<float4*>(out_n + (size_t)co * IMG + tilebase + px) = v;
        }
    }
}

extern "C" void kernel_launch(void* const* d_in, const int* in_sizes, int n_in,
                              void* d_out, int out_size)
{
    const float* x = (const float*)d_in[0];
    const float* w = (const float*)d_in[1];
    const float* b = (const float*)d_in[2];
    float* out = (float*)d_out;

    dim3 block(NTHREADS, 1, 1);
    dim3 grid(NN * BLKS_PER_IMG, 1, 1);   // 3136
    conv_mma<<<grid, block>>>(x, w, b, out);
}

// round 8
// speedup vs baseline: 1.3736x; 1.3736x over previous
#include <cuda_runtime.h>
#include <cstdint>

// Conv2d N=32, CIN=3, H=W=224, COUT=64, 3x3, s1, p1, fp32.
// Implicit GEMM via mma.sync.m16n8k16 bf16->f32, 3-pass hi/lo fp32 emulation.
// R8 = R4 (direct LDG gather, direct STG stores — best known: 103.9us)
//      + cross-iteration gather prefetch to hide load latency under the MMAs.

#define NN 32
#define HWDIM 224
#define IMG (HWDIM*HWDIM)        // 50176
#define COUT 64
#define CIN 3
#define NTHREADS 128
#define PX_PER_BLOCK 512
#define ITERS 8
#define BLKS_PER_IMG (IMG/PX_PER_BLOCK)   // 98

__device__ __forceinline__ uint32_t cvt_bf16x2(float hi, float lo) {
    uint32_t d;
    asm("cvt.rn.bf16x2.f32 %0, %1, %2;" : "=r"(d) : "f"(hi), "f"(lo));
    return d;
}
__device__ __forceinline__ void mma_bf16(float* d, const uint32_t* a, const uint32_t* b) {
    asm volatile(
        "mma.sync.aligned.m16n8k16.row.col.f32.bf16.bf16.f32 "
        "{%0,%1,%2,%3}, {%4,%5,%6,%7}, {%8,%9}, {%0,%1,%2,%3};"
        : "+f"(d[0]), "+f"(d[1]), "+f"(d[2]), "+f"(d[3])
        : "r"(a[0]), "r"(a[1]), "r"(a[2]), "r"(a[3]), "r"(b[0]), "r"(b[1]));
}

// Gather the 8 taps x 2 pixels for one warp-iteration directly from global.
__device__ __forceinline__ void gather_taps(
    const float* __restrict__ in_n, int p0,
    const int* coff, const int* dy, const int* dx,
    const bool* valid, const float* fdef,
    float* v0, float* v1)
{
    const int y  = p0 / HWDIM;
    const int x0 = p0 % HWDIM;
#pragma unroll
    for (int t = 0; t < 8; ++t) {
        const int  yy    = y + dy[t];
        const bool rowok = valid[t] && ((unsigned)yy < (unsigned)HWDIM);
        const float* rp  = in_n + coff[t] + yy * HWDIM;
        const int  xx0   = x0 + dx[t];
        const bool ok0   = rowok && ((unsigned)xx0 < (unsigned)HWDIM);
        const bool ok1   = rowok && (xx0 + 8 < HWDIM);
        const float dflt = valid[t] ? 0.f : fdef[t];
        v0[t] = ok0 ? __ldg(rp + xx0)     : dflt;
        v1[t] = ok1 ? __ldg(rp + xx0 + 8) : dflt;
    }
}

__global__ __launch_bounds__(NTHREADS, 3)
void conv_mma(const float* __restrict__ xin, const float* __restrict__ wgt,
              const float* __restrict__ bias, float* __restrict__ out)
{
    const int tid  = threadIdx.x;
    const int warp = tid >> 5;
    const int lane = tid & 31;
    const int lg   = lane >> 2;     // 0..7
    const int c    = (lane & 3) * 2;

    const int n   = blockIdx.x / BLKS_PER_IMG;
    const int blk = blockIdx.x % BLKS_PER_IMG;
    const float* in_n  = xin + (size_t)n * (CIN * IMG);
    float*       out_n = out + (size_t)n * (COUT * IMG);

    // ---- B (weight+bias) fragments, hi/lo, built once per thread ----
    uint32_t BH[8][2][2], BL[8][2][2];
#pragma unroll
    for (int nt = 0; nt < 8; ++nt) {
        const int co = nt * 8 + lg;
#pragma unroll
        for (int s = 0; s < 2; ++s)
#pragma unroll
        for (int r = 0; r < 2; ++r) {
            const int k0 = 16 * s + c + 8 * r;
            const int k1 = k0 + 1;
            const float f0 = (k0 < 27) ? wgt[co * 27 + k0] : (k0 == 27 ? bias[co] : 0.f);
            const float f1 = (k1 < 27) ? wgt[co * 27 + k1] : (k1 == 27 ? bias[co] : 0.f);
            const uint32_t h = cvt_bf16x2(f1, f0);
            const float l0 = f0 - __uint_as_float(h << 16);
            const float l1 = f1 - __uint_as_float(h & 0xffff0000u);
            BH[nt][s][r] = h;
            BL[nt][s][r] = cvt_bf16x2(l1, l0);
        }
    }

    // ---- tap descriptors: k = c + offs[t] ----
    const int offs[8] = {0, 1, 8, 9, 16, 17, 24, 25};
    int   coff[8], dy[8], dx[8];
    bool  valid[8];
    float fdef[8];
#pragma unroll
    for (int t = 0; t < 8; ++t) {
        const int k = c + offs[t];
        valid[t] = (k < 27);
        const int kk = valid[t] ? k : 0;
        const int ci = kk / 9, r = kk % 9;
        coff[t] = ci * IMG;
        dy[t]   = r / 3 - 1;
        dx[t]   = r % 3 - 1;
        fdef[t] = (k == 27) ? 1.f : 0.f;
    }

    const int pbase = blk * PX_PER_BLOCK + warp * 16 + lg;

    // ---- prologue: gather iteration 0 ----
    float v0[8], v1[8];
    gather_taps(in_n, pbase, coff, dy, dx, valid, fdef, v0, v1);

    for (int it = 0; it < ITERS; ++it) {
        // ---- split hi/lo, pack A fragments (v0/v1 die here) ----
        uint32_t AH[2][4], AL[2][4];
#pragma unroll
        for (int s = 0; s < 2; ++s)
#pragma unroll
        for (int r = 0; r < 2; ++r) {
            const int t0 = 4 * s + 2 * r;
            const float f00 = v0[t0], f01 = v0[t0 + 1];
            const float f10 = v1[t0], f11 = v1[t0 + 1];
            const uint32_t h0 = cvt_bf16x2(f01, f00);
            const uint32_t h1 = cvt_bf16x2(f11, f10);
            AH[s][2 * r]     = h0;
            AH[s][2 * r + 1] = h1;
            const float l00 = f00 - __uint_as_float(h0 << 16);
            const float l01 = f01 - __uint_as_float(h0 & 0xffff0000u);
            const float l10 = f10 - __uint_as_float(h1 << 16);
            const float l11 = f11 - __uint_as_float(h1 & 0xffff0000u);
            AL[s][2 * r]     = cvt_bf16x2(l01, l00);
            AL[s][2 * r + 1] = cvt_bf16x2(l11, l10);
        }

        // ---- prefetch next iteration's gathers (overlap with MMAs) ----
        if (it + 1 < ITERS)
            gather_taps(in_n, pbase + (it + 1) * 64, coff, dy, dx, valid, fdef, v0, v1);

        // ---- 48 MMAs ----
        float acc[8][4];
#pragma unroll
        for (int nt = 0; nt < 8; ++nt) {
            acc[nt][0] = 0.f; acc[nt][1] = 0.f; acc[nt][2] = 0.f; acc[nt][3] = 0.f;
        }
#pragma unroll
        for (int nt = 0; nt < 8; ++nt) {
#pragma unroll
            for (int s = 0; s < 2; ++s) {
                mma_bf16(acc[nt], AH[s], BH[nt][s]);
                mma_bf16(acc[nt], AH[s], BL[nt][s]);
                mma_bf16(acc[nt], AL[s], BH[nt][s]);
            }
        }

        // ---- store ----
        const int p0 = pbase + it * 64;
        const int p1 = p0 + 8;
#pragma unroll
        for (int nt = 0; nt < 8; ++nt) {
            const int co = nt * 8 + c;
            float* pl0 = out_n + (size_t)co * IMG;
            float* pl1 = pl0 + IMG;
            pl0[p0] = acc[nt][0];
            pl1[p0] = acc[nt][1];
            pl0[p1] = acc[nt][2];
            pl1[p1] = acc[nt][3];
        }
    }
}

extern "C" void kernel_launch(void* const* d_in, const int* in_sizes, int n_in,
                              void* d_out, int out_size)
{
    const float* x = (const float*)d_in[0];
    const float* w = (const float*)d_in[1];
    const float* b = (const float*)d_in[2];
    float* out = (float*)d_out;

    dim3 block(NTHREADS, 1, 1);
    dim3 grid(NN * BLKS_PER_IMG, 1, 1);   // 3136
    conv_mma<<<grid, block>>>(x, w, b, out);
}

// round 9
// speedup vs baseline: 1.3793x; 1.0041x over previous
#include <cuda_runtime.h>
#include <cstdint>

// Conv2d N=32, CIN=3, H=W=224, COUT=64, 3x3, s1, p1, fp32.
// Implicit GEMM via mma.sync.m16n8k16 bf16->f32, 3-pass hi/lo fp32 emulation.
// R9 = R8 + pixel-row permutation: MMA row r -> pixel 2*(r&7) + (r>>3), so each
// thread holds an ADJACENT pixel pair per co -> 16x STG.64 full-run stores
// (64 store wavefronts vs 128) and v1 gathers land on v0's cache line.

#define NN 32
#define HWDIM 224
#define IMG (HWDIM*HWDIM)        // 50176
#define COUT 64
#define CIN 3
#define NTHREADS 128
#define PX_PER_BLOCK 512
#define ITERS 8
#define BLKS_PER_IMG (IMG/PX_PER_BLOCK)   // 98

__device__ __forceinline__ uint32_t cvt_bf16x2(float hi, float lo) {
    uint32_t d;
    asm("cvt.rn.bf16x2.f32 %0, %1, %2;" : "=r"(d) : "f"(hi), "f"(lo));
    return d;
}
__device__ __forceinline__ void mma_bf16(float* d, const uint32_t* a, const uint32_t* b) {
    asm volatile(
        "mma.sync.aligned.m16n8k16.row.col.f32.bf16.bf16.f32 "
        "{%0,%1,%2,%3}, {%4,%5,%6,%7}, {%8,%9}, {%0,%1,%2,%3};"
        : "+f"(d[0]), "+f"(d[1]), "+f"(d[2]), "+f"(d[3])
        : "r"(a[0]), "r"(a[1]), "r"(a[2]), "r"(a[3]), "r"(b[0]), "r"(b[1]));
}

// Gather 8 taps for pixel pair (p0, p0+1). p0 is even and HWDIM is even,
// so both pixels share the image row.
__device__ __forceinline__ void gather_taps(
    const float* __restrict__ in_n, int p0,
    const int* coff, const int* dy, const int* dx,
    const bool* valid, const float* fdef,
    float* v0, float* v1)
{
    const int y  = p0 / HWDIM;
    const int x0 = p0 % HWDIM;
#pragma unroll
    for (int t = 0; t < 8; ++t) {
        const int  yy    = y + dy[t];
        const bool rowok = valid[t] && ((unsigned)yy < (unsigned)HWDIM);
        const float* rp  = in_n + coff[t] + yy * HWDIM;
        const int  xx0   = x0 + dx[t];
        const bool ok0   = rowok && ((unsigned)xx0 < (unsigned)HWDIM);
        const bool ok1   = rowok && ((unsigned)(xx0 + 1) < (unsigned)HWDIM);
        const float dflt = valid[t] ? 0.f : fdef[t];
        v0[t] = ok0 ? __ldg(rp + xx0)     : dflt;
        v1[t] = ok1 ? __ldg(rp + xx0 + 1) : dflt;
    }
}

__global__ __launch_bounds__(NTHREADS, 3)
void conv_mma(const float* __restrict__ xin, const float* __restrict__ wgt,
              const float* __restrict__ bias, float* __restrict__ out)
{
    const int tid  = threadIdx.x;
    const int warp = tid >> 5;
    const int lane = tid & 31;
    const int lg   = lane >> 2;     // 0..7
    const int c    = (lane & 3) * 2;

    const int n   = blockIdx.x / BLKS_PER_IMG;
    const int blk = blockIdx.x % BLKS_PER_IMG;
    const float* in_n  = xin + (size_t)n * (CIN * IMG);
    float*       out_n = out + (size_t)n * (COUT * IMG);

    // ---- B (weight+bias) fragments, hi/lo, built once per thread ----
    uint32_t BH[8][2][2], BL[8][2][2];
#pragma unroll
    for (int nt = 0; nt < 8; ++nt) {
        const int co = nt * 8 + lg;
#pragma unroll
        for (int s = 0; s < 2; ++s)
#pragma unroll
        for (int r = 0; r < 2; ++r) {
            const int k0 = 16 * s + c + 8 * r;
            const int k1 = k0 + 1;
            const float f0 = (k0 < 27) ? wgt[co * 27 + k0] : (k0 == 27 ? bias[co] : 0.f);
            const float f1 = (k1 < 27) ? wgt[co * 27 + k1] : (k1 == 27 ? bias[co] : 0.f);
            const uint32_t h = cvt_bf16x2(f1, f0);
            const float l0 = f0 - __uint_as_float(h << 16);
            const float l1 = f1 - __uint_as_float(h & 0xffff0000u);
            BH[nt][s][r] = h;
            BL[nt][s][r] = cvt_bf16x2(l1, l0);
        }
    }

    // ---- tap descriptors: k = c + offs[t] ----
    const int offs[8] = {0, 1, 8, 9, 16, 17, 24, 25};
    int   coff[8], dy[8], dx[8];
    bool  valid[8];
    float fdef[8];
#pragma unroll
    for (int t = 0; t < 8; ++t) {
        const int k = c + offs[t];
        valid[t] = (k < 27);
        const int kk = valid[t] ? k : 0;
        const int ci = kk / 9, r = kk % 9;
        coff[t] = ci * IMG;
        dy[t]   = r / 3 - 1;
        dx[t]   = r % 3 - 1;
        fdef[t] = (k == 27) ? 1.f : 0.f;
    }

    // A row lg -> pixel pbase (even), row lg+8 -> pixel pbase+1.
    const int pbase = blk * PX_PER_BLOCK + warp * 16 + 2 * lg;

    // ---- prologue: gather iteration 0 ----
    float v0[8], v1[8];
    gather_taps(in_n, pbase, coff, dy, dx, valid, fdef, v0, v1);

    for (int it = 0; it < ITERS; ++it) {
        // ---- split hi/lo, pack A fragments (v0/v1 die here) ----
        uint32_t AH[2][4], AL[2][4];
#pragma unroll
        for (int s = 0; s < 2; ++s)
#pragma unroll
        for (int r = 0; r < 2; ++r) {
            const int t0 = 4 * s + 2 * r;
            const float f00 = v0[t0], f01 = v0[t0 + 1];
            const float f10 = v1[t0], f11 = v1[t0 + 1];
            const uint32_t h0 = cvt_bf16x2(f01, f00);
            const uint32_t h1 = cvt_bf16x2(f11, f10);
            AH[s][2 * r]     = h0;
            AH[s][2 * r + 1] = h1;
            const float l00 = f00 - __uint_as_float(h0 << 16);
            const float l01 = f01 - __uint_as_float(h0 & 0xffff0000u);
            const float l10 = f10 - __uint_as_float(h1 << 16);
            const float l11 = f11 - __uint_as_float(h1 & 0xffff0000u);
            AL[s][2 * r]     = cvt_bf16x2(l01, l00);
            AL[s][2 * r + 1] = cvt_bf16x2(l11, l10);
        }

        // ---- prefetch next iteration's gathers (overlap with MMAs) ----
        if (it + 1 < ITERS)
            gather_taps(in_n, pbase + (it + 1) * 64, coff, dy, dx, valid, fdef, v0, v1);

        // ---- 48 MMAs ----
        float acc[8][4];
#pragma unroll
        for (int nt = 0; nt < 8; ++nt) {
            acc[nt][0] = 0.f; acc[nt][1] = 0.f; acc[nt][2] = 0.f; acc[nt][3] = 0.f;
        }
#pragma unroll
        for (int nt = 0; nt < 8; ++nt) {
#pragma unroll
            for (int s = 0; s < 2; ++s) {
                mma_bf16(acc[nt], AH[s], BH[nt][s]);
                mma_bf16(acc[nt], AH[s], BL[nt][s]);
                mma_bf16(acc[nt], AL[s], BH[nt][s]);
            }
        }

        // ---- store: per co, float2 of adjacent pixels (p0, p0+1) ----
        // D regs: c0=(p0,co c) c1=(p0,co c+1) c2=(p0+1,co c) c3=(p0+1,co c+1)
        const int p0 = pbase + it * 64;   // even -> 8B aligned
#pragma unroll
        for (int nt = 0; nt < 8; ++nt) {
            const int co = nt * 8 + c;
            float* pl0 = out_n + (size_t)co * IMG + p0;
            float* pl1 = pl0 + IMG;
            *reinterpret_cast<float2*>(pl0) = make_float2(acc[nt][0], acc[nt][2]);
            *reinterpret_cast<float2*>(pl1) = make_float2(acc[nt][1], acc[nt][3]);
        }
    }
}

extern "C" void kernel_launch(void* const* d_in, const int* in_sizes, int n_in,
                              void* d_out, int out_size)
{
    const float* x = (const float*)d_in[0];
    const float* w = (const float*)d_in[1];
    const float* b = (const float*)d_in[2];
    float* out = (float*)d_out;

    dim3 block(NTHREADS, 1, 1);
    dim3 grid(NN * BLKS_PER_IMG, 1, 1);   // 3136
    conv_mma<<<grid, block>>>(x, w, b, out);
}